// round 13
// baseline (speedup 1.0000x reference)
#include <cuda_runtime.h>
#include <mma.h>
#include <cuda_fp16.h>
#include <cstddef>
#include <cstdint>

using namespace nvcuda;

#define NN 100000
#define NN_PAD 100096            // 782 * 128
#define NE 1600000
#define SCAN_B 1024
#define NBLK ((NN + SCAN_B - 1) / SCAN_B)   // 98
#define KF 272                   // fused K: 128 (h) + 128 (agg) + 16 (bias+pad)
#define AGS 144                  // agg row stride in halves (128 + 1 one + 15 zero)

// ---------------- scratch ---------------------------------------------------
__device__ __half g_hA[(size_t)NN_PAD * 128];  // h buffer A (x16 / h2)
__device__ __half g_hB[(size_t)NN_PAD * 128];  // h buffer B (h1)
__device__ __half g_ag[(size_t)NN_PAD * AGS];  // [agg | 1 | 0pad] per node
__device__ float  g_y[(size_t)NN_PAD * 128];   // fp32 GEMM out (y / h32)
__device__ float  g_z[(size_t)NN_PAD * 128];   // z (layer 0 only)
__device__ __half g_yh[(size_t)NN * 128];      // y fp16 (layer 0 gather)
__device__ __half g_wc0[256 * 128];            // layer0 [Wl0;Wr0] fp16
__device__ __half g_wf1[128 * KF];             // layer1 fused [Wr|Wl|b|0]
__device__ __half g_wf2[64 * KF];              // layer2 fused
__device__ int    g_cnt[NN];
__device__ int    g_offs[NN + 1];
__device__ int    g_cursor[NN];
__device__ int    g_csrc[NE];
__device__ int    g_bsum[NBLK];

// ---------------- helpers ---------------------------------------------------
__device__ __forceinline__ uint4 pack8h(float4 f0, float4 f1) {
    union { uint4 u; __half2 h[4]; } P;
    P.h[0] = __floats2half2_rn(f0.x, f0.y);
    P.h[1] = __floats2half2_rn(f0.z, f0.w);
    P.h[2] = __floats2half2_rn(f1.x, f1.y);
    P.h[3] = __floats2half2_rn(f1.z, f1.w);
    return P.u;
}
__device__ __forceinline__ uint32_t smem_u32(const void* p) {
    return (uint32_t)__cvta_generic_to_shared(p);
}
#define CPA(dst, src) \
    asm volatile("cp.async.cg.shared.global [%0], [%1], 16;" :: "r"(dst), "l"(src))
#define CPC() asm volatile("cp.async.commit_group;")
#define CPW(n) asm volatile("cp.async.wait_group %0;" :: "n"(n))

// ---------------- CSR build -------------------------------------------------
__global__ void count_deg(const int* __restrict__ dst, int* __restrict__ cnt) {
    int e = blockIdx.x * blockDim.x + threadIdx.x;
    if (e < NE) atomicAdd(cnt + dst[e], 1);
}
__global__ void zero_cnt(int* __restrict__ cnt) {
    int i = blockIdx.x * blockDim.x + threadIdx.x;
    if (i < NN) cnt[i] = 0;
}
__global__ void scan_a(const int* __restrict__ cnt, int* __restrict__ offs,
                       int* __restrict__ bsum) {
    __shared__ int sh[SCAN_B];
    int gid = blockIdx.x * SCAN_B + threadIdx.x;
    int v = (gid < NN) ? cnt[gid] : 0;
    sh[threadIdx.x] = v;
    __syncthreads();
    for (int d = 1; d < SCAN_B; d <<= 1) {
        int t = (threadIdx.x >= d) ? sh[threadIdx.x - d] : 0;
        __syncthreads();
        sh[threadIdx.x] += t;
        __syncthreads();
    }
    if (gid < NN) offs[gid] = sh[threadIdx.x] - v;
    if (threadIdx.x == SCAN_B - 1) bsum[blockIdx.x] = sh[threadIdx.x];
}
__global__ void scan_b(int* __restrict__ bsum) {
    __shared__ int sh[128];
    int v = (threadIdx.x < NBLK) ? bsum[threadIdx.x] : 0;
    sh[threadIdx.x] = v;
    __syncthreads();
    for (int d = 1; d < 128; d <<= 1) {
        int t = (threadIdx.x >= d) ? sh[threadIdx.x - d] : 0;
        __syncthreads();
        sh[threadIdx.x] += t;
        __syncthreads();
    }
    if (threadIdx.x < NBLK) bsum[threadIdx.x] = sh[threadIdx.x] - v;
}
__global__ void scan_c(int* __restrict__ offs, const int* __restrict__ bsum,
                       int* __restrict__ cursor) {
    int gid = blockIdx.x * blockDim.x + threadIdx.x;
    if (gid < NN) {
        int o = offs[gid] + bsum[gid >> 10];
        offs[gid] = o;
        cursor[gid] = o;
    }
    if (gid == 0) offs[NN] = NE;
}
__global__ void place_edges(const int* __restrict__ src, const int* __restrict__ dst,
                            int* __restrict__ cursor, int* __restrict__ csrc) {
    int e = blockIdx.x * blockDim.x + threadIdx.x;
    if (e < NE) {
        int p = atomicAdd(cursor + dst[e], 1);
        csrc[p] = src[e];
    }
}

// ---------------- fp16 conversions -------------------------------------------
__global__ void cvt_x_h(const float4* __restrict__ in, uint4* __restrict__ out) {
    int i = blockIdx.x * blockDim.x + threadIdx.x;
    if (i >= NN_PAD * 16) return;
    uint4 u = make_uint4(0u, 0u, 0u, 0u);
    if (i < NN * 16) u = pack8h(in[2 * i], in[2 * i + 1]);
    out[i] = u;
}
// layer-0 weights: [Wl ; Wr] fp16 concat (rows), stride 128.
__global__ void cvt_w_h(const float4* __restrict__ Wl, const float4* __restrict__ Wr,
                        uint4* __restrict__ out, int n8half) {
    int i = blockIdx.x * blockDim.x + threadIdx.x;
    if (i < n8half)
        out[i] = pack8h(Wl[2 * i], Wl[2 * i + 1]);
    else if (i < 2 * n8half) {
        int j = i - n8half;
        out[i] = pack8h(Wr[2 * j], Wr[2 * j + 1]);
    }
}
// fused weights: row n = [Wr_n(128) | Wl_n(128) | b_n | 0 x15], stride KF=272.
__global__ void cvt_w_f(const float4* __restrict__ Wl, const float4* __restrict__ Wr,
                        const float* __restrict__ b, uint4* __restrict__ out,
                        int nrows) {
    int i = blockIdx.x * blockDim.x + threadIdx.x;
    if (i >= nrows * 34) return;              // 34 uint4 per row (272 halves)
    int n = i / 34, s = i % 34;
    uint4 v = make_uint4(0u, 0u, 0u, 0u);
    if (s < 16)
        v = pack8h(Wr[n * 32 + 2 * s], Wr[n * 32 + 2 * s + 1]);
    else if (s < 32) {
        int t = s - 16;
        v = pack8h(Wl[n * 32 + 2 * t], Wl[n * 32 + 2 * t + 1]);
    } else if (s == 32) {
        __half hb = __float2half_rn(b[n]);
        v.x = (uint32_t)__half_as_ushort(hb);  // low half = bias, rest 0
    }
    out[n * 34 + s] = v;
}
// y fp32 -> fp16 streaming, n uint4s.
__global__ void cvt_y(const float4* __restrict__ in, uint4* __restrict__ out,
                      int n) {
    int i = blockIdx.x * blockDim.x + threadIdx.x;
    if (i >= n) return;
    out[i] = pack8h(in[2 * i], in[2 * i + 1]);
}
// h32 fp32 -> fp16 over NN_PAD rows.
__global__ void cvt_h(const float4* __restrict__ in, uint4* __restrict__ out) {
    int i = blockIdx.x * blockDim.x + threadIdx.x;
    if (i >= NN_PAD * 16) return;
    out[i] = pack8h(in[2 * i], in[2 * i + 1]);
}

// ---------------- mean-aggregate h -> agg buffer (fp16) ----------------------
// AG row (stride 144): [mean(128) | 1.0 | 0 x15]. Pad nodes: zeros + 1.0.
__global__ void agg_h(const uint4* __restrict__ h4,
                      const int* __restrict__ csrc,
                      const int* __restrict__ offs,
                      uint4* __restrict__ ag) {
    int gid = blockIdx.x * blockDim.x + threadIdx.x;
    int node = gid / 16;
    int lane = gid % 16;
    if (node >= NN_PAD) return;

    uint4 w = make_uint4(0u, 0u, 0u, 0u);
    if (node < NN) {
        int s = offs[node], e = offs[node + 1];
        float a[8] = {0.f, 0.f, 0.f, 0.f, 0.f, 0.f, 0.f, 0.f};
        int i = s;
        for (; i + 1 < e; i += 2) {
            uint4 u0 = h4[(size_t)csrc[i] * 16 + lane];
            uint4 u1 = h4[(size_t)csrc[i + 1] * 16 + lane];
            const __half2* p0 = (const __half2*)&u0;
            const __half2* p1 = (const __half2*)&u1;
            #pragma unroll
            for (int k = 0; k < 4; k++) {
                float2 f0 = __half22float2(p0[k]);
                float2 f1 = __half22float2(p1[k]);
                a[2 * k]     += f0.x + f1.x;
                a[2 * k + 1] += f0.y + f1.y;
            }
        }
        if (i < e) {
            uint4 u = h4[(size_t)csrc[i] * 16 + lane];
            const __half2* p = (const __half2*)&u;
            #pragma unroll
            for (int k = 0; k < 4; k++) {
                float2 f = __half22float2(p[k]);
                a[2 * k]     += f.x;
                a[2 * k + 1] += f.y;
            }
        }
        float inv = 1.0f / (float)max(e - s, 1);
        float4 m0 = make_float4(a[0] * inv, a[1] * inv, a[2] * inv, a[3] * inv);
        float4 m1 = make_float4(a[4] * inv, a[5] * inv, a[6] * inv, a[7] * inv);
        w = pack8h(m0, m1);
    }
    ag[(size_t)node * 18 + lane] = w;
    if (lane == 0)
        ag[(size_t)node * 18 + 16] = make_uint4(0x00003C00u, 0u, 0u, 0u); // 1.0
    else if (lane == 1)
        ag[(size_t)node * 18 + 17] = make_uint4(0u, 0u, 0u, 0u);
}

// ---------------- FP16 GEMM, layer 0 (K=128, split Y/Z) — proven R12 ---------
#define LDTH 24

__global__ __launch_bounds__(256, 2) void h16gemm(
    const __half* __restrict__ A, const __half* __restrict__ B,
    float* __restrict__ Y, float* __restrict__ Z, int N) {
    __shared__ __half As[2][128][LDTH];
    __shared__ __half Bs[2][128][LDTH];

    const int tid = threadIdx.x;
    const int warp = tid >> 5;
    const int wm = warp & 3;
    const int wn = warp >> 2;
    const int bm0 = blockIdx.y * 128;
    const int bn0 = blockIdx.x * 128;

    wmma::fragment<wmma::accumulator, 16, 16, 16, float> acc[2][4];
    #pragma unroll
    for (int i = 0; i < 2; i++)
        #pragma unroll
        for (int j = 0; j < 4; j++)
            wmma::fill_fragment(acc[i][j], 0.0f);

    const int r = tid >> 1;
    const int c = (tid & 1) * 8;
    const __half* Ap = A + (size_t)(bm0 + r) * 128 + c;
    const __half* Bp = B + (size_t)(bn0 + r) * 128 + c;
    const uint32_t sA = smem_u32(&As[0][r][c]);
    const uint32_t sB = smem_u32(&Bs[0][r][c]);
    const uint32_t STG = 128 * LDTH * 2;

    CPA(sA, Ap); CPA(sB, Bp); CPC();

    #pragma unroll
    for (int t = 0; t < 8; t++) {
        const int cur = t & 1;
        if (t < 7) {
            const uint32_t so = ((t + 1) & 1) * STG;
            const int k0 = (t + 1) * 16;
            CPA(sA + so, Ap + k0);
            CPA(sB + so, Bp + k0);
            CPC();
            CPW(1);
        } else {
            CPW(0);
        }
        __syncthreads();

        wmma::fragment<wmma::matrix_a, 16, 16, 16, __half, wmma::row_major> af[2];
        wmma::fragment<wmma::matrix_b, 16, 16, 16, __half, wmma::col_major> bf[4];
        wmma::load_matrix_sync(af[0], &As[cur][wm * 32 + 0][0], LDTH);
        wmma::load_matrix_sync(af[1], &As[cur][wm * 32 + 16][0], LDTH);
        #pragma unroll
        for (int j = 0; j < 4; j++)
            wmma::load_matrix_sync(bf[j], &Bs[cur][wn * 64 + j * 16][0], LDTH);
        #pragma unroll
        for (int i = 0; i < 2; i++)
            #pragma unroll
            for (int j = 0; j < 4; j++)
                wmma::mma_sync(acc[i][j], af[i], bf[j], acc[i][j]);

        __syncthreads();
    }

    const int halfN = N >> 1;
    const int slab0 = bn0 + wn * 64;
    float* Cb = (slab0 < halfN) ? Y : Z;
    const int ccol = (slab0 < halfN) ? slab0 : slab0 - halfN;
    #pragma unroll
    for (int i = 0; i < 2; i++)
        #pragma unroll
        for (int j = 0; j < 4; j++) {
            int row0 = bm0 + wm * 32 + i * 16;
            wmma::store_matrix_sync(Cb + (size_t)row0 * halfN + ccol + j * 16,
                                    acc[i][j], halfN, wmma::mem_row_major);
        }
}

// ---------------- fused GEMM, layers 1 (N=128): C = relu([h|agg|1]@Wf^T) -----
// A1 = h (stride 128), A2 = agg (stride 144), B stride 272, K=272 (17 iters).
__global__ __launch_bounds__(256, 2) void h16gemm_f128(
    const __half* __restrict__ A1, const __half* __restrict__ A2,
    const __half* __restrict__ B, float* __restrict__ C) {
    __shared__ __half As[2][128][LDTH];
    __shared__ __half Bs[2][128][LDTH];

    const int tid = threadIdx.x;
    const int warp = tid >> 5;
    const int wm = warp & 3;
    const int wn = warp >> 2;
    const int bm0 = blockIdx.y * 128;

    wmma::fragment<wmma::accumulator, 16, 16, 16, float> acc[2][4];
    #pragma unroll
    for (int i = 0; i < 2; i++)
        #pragma unroll
        for (int j = 0; j < 4; j++)
            wmma::fill_fragment(acc[i][j], 0.0f);

    const int r = tid >> 1;
    const int c = (tid & 1) * 8;
    const __half* Ap1 = A1 + (size_t)(bm0 + r) * 128 + c;
    const __half* Ap2 = A2 + (size_t)(bm0 + r) * AGS + c;
    const __half* Bp  = B + (size_t)r * KF + c;
    const uint32_t sA = smem_u32(&As[0][r][c]);
    const uint32_t sB = smem_u32(&Bs[0][r][c]);
    const uint32_t STG = 128 * LDTH * 2;

    CPA(sA, Ap1); CPA(sB, Bp); CPC();

    #pragma unroll
    for (int t = 0; t < 17; t++) {
        const int cur = t & 1;
        if (t < 16) {
            const int tt = t + 1;
            const uint32_t so = (tt & 1) * STG;
            const __half* asrc = (tt < 8) ? (Ap1 + tt * 16)
                                          : (Ap2 + tt * 16 - 128);
            CPA(sA + so, asrc);
            CPA(sB + so, Bp + tt * 16);
            CPC();
            CPW(1);
        } else {
            CPW(0);
        }
        __syncthreads();

        wmma::fragment<wmma::matrix_a, 16, 16, 16, __half, wmma::row_major> af[2];
        wmma::fragment<wmma::matrix_b, 16, 16, 16, __half, wmma::col_major> bf[4];
        wmma::load_matrix_sync(af[0], &As[cur][wm * 32 + 0][0], LDTH);
        wmma::load_matrix_sync(af[1], &As[cur][wm * 32 + 16][0], LDTH);
        #pragma unroll
        for (int j = 0; j < 4; j++)
            wmma::load_matrix_sync(bf[j], &Bs[cur][wn * 64 + j * 16][0], LDTH);
        #pragma unroll
        for (int i = 0; i < 2; i++)
            #pragma unroll
            for (int j = 0; j < 4; j++)
                wmma::mma_sync(acc[i][j], af[i], bf[j], acc[i][j]);

        __syncthreads();
    }

    // relu elementwise (mapping-free), fp32 store, all NN_PAD rows.
    #pragma unroll
    for (int i = 0; i < 2; i++)
        #pragma unroll
        for (int j = 0; j < 4; j++) {
            #pragma unroll
            for (int e = 0; e < acc[i][j].num_elements; e++)
                acc[i][j].x[e] = fmaxf(acc[i][j].x[e], 0.0f);
            int row0 = bm0 + wm * 32 + i * 16;
            wmma::store_matrix_sync(C + (size_t)row0 * 128 + wn * 64 + j * 16,
                                    acc[i][j], 128, wmma::mem_row_major);
        }
}

// ---------------- fused GEMM, layer 2 (N=64, no relu, fp32 out) --------------
// Block 128x64, warps 4x2, warp tile 32x32; rows >= NN not stored.
__global__ __launch_bounds__(256, 2) void h16gemm_f64(
    const __half* __restrict__ A1, const __half* __restrict__ A2,
    const __half* __restrict__ B, float* __restrict__ C) {
    __shared__ __half As[2][128][LDTH];
    __shared__ __half Bs[2][64][LDTH];

    const int tid = threadIdx.x;
    const int warp = tid >> 5;
    const int wm = warp & 3;
    const int wn = warp >> 2;
    const int bm0 = blockIdx.y * 128;

    wmma::fragment<wmma::accumulator, 16, 16, 16, float> acc[2][2];
    #pragma unroll
    for (int i = 0; i < 2; i++)
        #pragma unroll
        for (int j = 0; j < 2; j++)
            wmma::fill_fragment(acc[i][j], 0.0f);

    const int r = tid >> 1;
    const int c = (tid & 1) * 8;
    const __half* Ap1 = A1 + (size_t)(bm0 + r) * 128 + c;
    const __half* Ap2 = A2 + (size_t)(bm0 + r) * AGS + c;
    const __half* Bp  = B + (size_t)r * KF + c;      // valid for r < 64
    const uint32_t sA = smem_u32(&As[0][r][c]);
    const bool bload = tid < 128;                    // 64 rows x 16 halves
    const uint32_t sB = bload ? smem_u32(&Bs[0][r][c]) : 0u;
    const uint32_t STGA = 128 * LDTH * 2;
    const uint32_t STGB = 64 * LDTH * 2;

    CPA(sA, Ap1);
    if (bload) CPA(sB, Bp);
    CPC();

    #pragma unroll
    for (int t = 0; t < 17; t++) {
        const int cur = t & 1;
        if (t < 16) {
            const int tt = t + 1;
            const __half* asrc = (tt < 8) ? (Ap1 + tt * 16)
                                          : (Ap2 + tt * 16 - 128);
            CPA(sA + (tt & 1) * STGA, asrc);
            if (bload) CPA(sB + (tt & 1) * STGB, Bp + tt * 16);
            CPC();
            CPW(1);
        } else {
            CPW(0);
        }
        __syncthreads();

        wmma::fragment<wmma::matrix_a, 16, 16, 16, __half, wmma::row_major> af[2];
        wmma::fragment<wmma::matrix_b, 16, 16, 16, __half, wmma::col_major> bf[2];
        wmma::load_matrix_sync(af[0], &As[cur][wm * 32 + 0][0], LDTH);
        wmma::load_matrix_sync(af[1], &As[cur][wm * 32 + 16][0], LDTH);
        #pragma unroll
        for (int j = 0; j < 2; j++)
            wmma::load_matrix_sync(bf[j], &Bs[cur][wn * 32 + j * 16][0], LDTH);
        #pragma unroll
        for (int i = 0; i < 2; i++)
            #pragma unroll
            for (int j = 0; j < 2; j++)
                wmma::mma_sync(acc[i][j], af[i], bf[j], acc[i][j]);

        __syncthreads();
    }

    #pragma unroll
    for (int i = 0; i < 2; i++) {
        int row0 = bm0 + wm * 32 + i * 16;
        if (row0 < NN) {       // NN multiple of 16 -> fragments all-in/all-out
            #pragma unroll
            for (int j = 0; j < 2; j++)
                wmma::store_matrix_sync(C + (size_t)row0 * 64 + wn * 32 + j * 16,
                                        acc[i][j], 64, wmma::mem_row_major);
        }
    }
}

// ---------------- layer-0 aggregate + combine (R12, fp16 y gather) -----------
template <int HL>
__global__ void agg_combine0(const uint4* __restrict__ yh4,
                             const float4* __restrict__ z4,
                             const int* __restrict__ csrc,
                             const int* __restrict__ offs,
                             const float* __restrict__ b,
                             uint4* __restrict__ outh) {
    int gid = blockIdx.x * blockDim.x + threadIdx.x;
    int node = gid / HL;
    int lane = gid % HL;
    if (node >= NN_PAD) return;
    if (node >= NN) {
        outh[(size_t)node * HL + lane] = make_uint4(0u, 0u, 0u, 0u);
        return;
    }

    int s = offs[node], e = offs[node + 1];
    float a[8] = {0.f, 0.f, 0.f, 0.f, 0.f, 0.f, 0.f, 0.f};
    int i = s;
    for (; i + 1 < e; i += 2) {
        uint4 u0 = yh4[(size_t)csrc[i] * HL + lane];
        uint4 u1 = yh4[(size_t)csrc[i + 1] * HL + lane];
        const __half2* p0 = (const __half2*)&u0;
        const __half2* p1 = (const __half2*)&u1;
        #pragma unroll
        for (int k = 0; k < 4; k++) {
            float2 f0 = __half22float2(p0[k]);
            float2 f1 = __half22float2(p1[k]);
            a[2 * k]     += f0.x + f1.x;
            a[2 * k + 1] += f0.y + f1.y;
        }
    }
    if (i < e) {
        uint4 u = yh4[(size_t)csrc[i] * HL + lane];
        const __half2* p = (const __half2*)&u;
        #pragma unroll
        for (int k = 0; k < 4; k++) {
            float2 f = __half22float2(p[k]);
            a[2 * k]     += f.x;
            a[2 * k + 1] += f.y;
        }
    }

    float inv = 1.0f / (float)max(e - s, 1);
    float4 z0 = z4[(size_t)node * 2 * HL + lane * 2 + 0];
    float4 z1 = z4[(size_t)node * 2 * HL + lane * 2 + 1];
    float4 bb0 = ((const float4*)b)[lane * 2 + 0];
    float4 bb1 = ((const float4*)b)[lane * 2 + 1];
    float4 o0, o1;
    o0.x = fmaxf(a[0] * inv + z0.x + bb0.x, 0.f);
    o0.y = fmaxf(a[1] * inv + z0.y + bb0.y, 0.f);
    o0.z = fmaxf(a[2] * inv + z0.z + bb0.z, 0.f);
    o0.w = fmaxf(a[3] * inv + z0.w + bb0.w, 0.f);
    o1.x = fmaxf(a[4] * inv + z1.x + bb1.x, 0.f);
    o1.y = fmaxf(a[5] * inv + z1.y + bb1.y, 0.f);
    o1.z = fmaxf(a[6] * inv + z1.z + bb1.z, 0.f);
    o1.w = fmaxf(a[7] * inv + z1.w + bb1.w, 0.f);
    outh[(size_t)node * HL + lane] = pack8h(o0, o1);
}

// ---------------------------------------------------------------------------
extern "C" void kernel_launch(void* const* d_in, const int* in_sizes, int n_in,
                              void* d_out, int out_size) {
    const float* x   = (const float*)d_in[0];
    const int*   ei  = (const int*)d_in[1];
    const float* Wl0 = (const float*)d_in[2];
    const float* Wr0 = (const float*)d_in[3];
    const float* b0  = (const float*)d_in[4];
    const float* Wl1 = (const float*)d_in[5];
    const float* Wr1 = (const float*)d_in[6];
    const float* b1  = (const float*)d_in[7];
    const float* Wl2 = (const float*)d_in[8];
    const float* Wr2 = (const float*)d_in[9];
    const float* b2  = (const float*)d_in[10];
    float* out = (float*)d_out;

    const int* src = ei;
    const int* dst = ei + NE;

    __half *hA, *hB, *ag, *yh, *wc0, *wf1, *wf2;
    float *y, *z;
    int *cnt, *offs, *cursor, *csrc, *bsum;
    cudaGetSymbolAddress((void**)&hA,   g_hA);
    cudaGetSymbolAddress((void**)&hB,   g_hB);
    cudaGetSymbolAddress((void**)&ag,   g_ag);
    cudaGetSymbolAddress((void**)&y,    g_y);
    cudaGetSymbolAddress((void**)&z,    g_z);
    cudaGetSymbolAddress((void**)&yh,   g_yh);
    cudaGetSymbolAddress((void**)&wc0,  g_wc0);
    cudaGetSymbolAddress((void**)&wf1,  g_wf1);
    cudaGetSymbolAddress((void**)&wf2,  g_wf2);
    cudaGetSymbolAddress((void**)&cnt,  g_cnt);
    cudaGetSymbolAddress((void**)&offs, g_offs);
    cudaGetSymbolAddress((void**)&cursor, g_cursor);
    cudaGetSymbolAddress((void**)&csrc, g_csrc);
    cudaGetSymbolAddress((void**)&bsum, g_bsum);

    const int T = 256;
    dim3 gM(2, NN_PAD / 128);    // layer0 GEMM: N = 256
    dim3 gF(1, NN_PAD / 128);    // fused GEMMs

    // Fork/join side stream (verified pattern).
    cudaStream_t s2;
    cudaEvent_t evFork, evJoin;
    cudaStreamCreateWithFlags(&s2, cudaStreamNonBlocking);
    cudaEventCreateWithFlags(&evFork, cudaEventDisableTiming);
    cudaEventCreateWithFlags(&evJoin, cudaEventDisableTiming);

    cudaEventRecord(evFork, 0);
    cudaStreamWaitEvent(s2, evFork, 0);

    // ---- main: fp16 prep + layer-0 GEMM (4th kernel launch for ncu) ----
    cvt_x_h<<<(NN_PAD * 16 + T - 1) / T, T>>>((const float4*)x, (uint4*)hA); // 1
    cvt_w_h<<<(2 * 2048 + T - 1) / T, T>>>((const float4*)Wl0,
                                           (const float4*)Wr0,
                                           (uint4*)wc0, 2048);               // 2
    zero_cnt<<<(NN + T - 1) / T, T, 0, s2>>>(cnt);                           // 3 (s2)
    h16gemm<<<gM, T>>>(hA, wc0, y, z, 256);                                  // 4 <- ncu
    cvt_y<<<(NN * 16 + T - 1) / T, T>>>((const float4*)y, (uint4*)yh, NN * 16);

    // ---- side stream: CSR build + fused weight prep ----
    count_deg<<<(NE + T - 1) / T, T, 0, s2>>>(dst, cnt);
    scan_a<<<NBLK, SCAN_B, 0, s2>>>(cnt, offs, bsum);
    scan_b<<<1, 128, 0, s2>>>(bsum);
    scan_c<<<(NN + T - 1) / T, T, 0, s2>>>(offs, bsum, cursor);
    place_edges<<<(NE + T - 1) / T, T, 0, s2>>>(src, dst, cursor, csrc);
    cvt_w_f<<<(128 * 34 + T - 1) / T, T, 0, s2>>>((const float4*)Wl1,
                                                  (const float4*)Wr1, b1,
                                                  (uint4*)wf1, 128);
    cvt_w_f<<<(64 * 34 + T - 1) / T, T, 0, s2>>>((const float4*)Wl2,
                                                 (const float4*)Wr2, b2,
                                                 (uint4*)wf2, 64);
    cudaEventRecord(evJoin, s2);
    cudaStreamWaitEvent(0, evJoin, 0);

    // ---- layer 0 combine -> h1 (fp16, hB) ----
    agg_combine0<16><<<(NN_PAD * 16 + T - 1) / T, T>>>(
        (const uint4*)yh, (const float4*)z, csrc, offs, b0, (uint4*)hB);

    // ---- layer 1 (fused): agg(h1) -> GEMM -> relu -> h2 ----
    agg_h<<<(NN_PAD * 16 + T - 1) / T, T>>>((const uint4*)hB, csrc, offs,
                                            (uint4*)ag);
    h16gemm_f128<<<gF, T>>>(hB, ag, wf1, y);
    cvt_h<<<(NN_PAD * 16 + T - 1) / T, T>>>((const float4*)y, (uint4*)hA);

    // ---- layer 2 (fused): agg(h2) -> GEMM -> out (fp32, no relu) ----
    agg_h<<<(NN_PAD * 16 + T - 1) / T, T>>>((const uint4*)hA, csrc, offs,
                                            (uint4*)ag);
    h16gemm_f64<<<gF, T>>>(hA, ag, wf2, out);
}

// round 14
// speedup vs baseline: 1.0627x; 1.0627x over previous
#include <cuda_runtime.h>
#include <mma.h>
#include <cuda_fp16.h>
#include <cstddef>
#include <cstdint>

using namespace nvcuda;

#define NN 100000
#define NN_PAD 100096            // 782 * 128
#define NE 1600000
#define SCAN_B 1024
#define NBLK ((NN + SCAN_B - 1) / SCAN_B)   // 98

// ---------------- scratch ---------------------------------------------------
__device__ __half g_x[(size_t)NN_PAD * 128];   // x in fp16 (padded, zeroed)
__device__ float  g_y[(size_t)NN_PAD * 128];   // y fp32 (layer-2 GEMM out only)
__device__ __half g_yh[(size_t)NN_PAD * 128];  // y fp16 (gathered over edges)
__device__ float  g_z[(size_t)NN_PAD * 128];   // z fp32
__device__ __half g_h[(size_t)NN_PAD * 128];   // activations fp16 (padded)
__device__ __half g_wcat[3][256 * 128];        // fp16 [Wl ; Wr] per layer
__device__ int    g_cnt[NN];
__device__ int    g_offs[NN + 1];
__device__ int    g_cursor[NN];
__device__ int    g_csrc[NE];
__device__ int    g_bsum[NBLK];

// ---------------- helpers ---------------------------------------------------
__device__ __forceinline__ uint4 pack8h(float4 f0, float4 f1) {
    union { uint4 u; __half2 h[4]; } P;
    P.h[0] = __floats2half2_rn(f0.x, f0.y);
    P.h[1] = __floats2half2_rn(f0.z, f0.w);
    P.h[2] = __floats2half2_rn(f1.x, f1.y);
    P.h[3] = __floats2half2_rn(f1.z, f1.w);
    return P.u;
}
__device__ __forceinline__ uint32_t smem_u32(const void* p) {
    return (uint32_t)__cvta_generic_to_shared(p);
}
#define CPA(dst, src) \
    asm volatile("cp.async.cg.shared.global [%0], [%1], 16;" :: "r"(dst), "l"(src))
#define CPC() asm volatile("cp.async.commit_group;")
#define CPW(n) asm volatile("cp.async.wait_group %0;" :: "n"(n))

// ---------------- CSR build -------------------------------------------------
__global__ void count_deg(const int* __restrict__ dst, int* __restrict__ cnt) {
    int e = blockIdx.x * blockDim.x + threadIdx.x;
    if (e < NE) atomicAdd(cnt + dst[e], 1);
}
__global__ void zero_cnt(int* __restrict__ cnt) {
    int i = blockIdx.x * blockDim.x + threadIdx.x;
    if (i < NN) cnt[i] = 0;
}
__global__ void scan_a(const int* __restrict__ cnt, int* __restrict__ offs,
                       int* __restrict__ bsum) {
    __shared__ int sh[SCAN_B];
    int gid = blockIdx.x * SCAN_B + threadIdx.x;
    int v = (gid < NN) ? cnt[gid] : 0;
    sh[threadIdx.x] = v;
    __syncthreads();
    for (int d = 1; d < SCAN_B; d <<= 1) {
        int t = (threadIdx.x >= d) ? sh[threadIdx.x - d] : 0;
        __syncthreads();
        sh[threadIdx.x] += t;
        __syncthreads();
    }
    if (gid < NN) offs[gid] = sh[threadIdx.x] - v;
    if (threadIdx.x == SCAN_B - 1) bsum[blockIdx.x] = sh[threadIdx.x];
}
__global__ void scan_b(int* __restrict__ bsum) {
    __shared__ int sh[128];
    int v = (threadIdx.x < NBLK) ? bsum[threadIdx.x] : 0;
    sh[threadIdx.x] = v;
    __syncthreads();
    for (int d = 1; d < 128; d <<= 1) {
        int t = (threadIdx.x >= d) ? sh[threadIdx.x - d] : 0;
        __syncthreads();
        sh[threadIdx.x] += t;
        __syncthreads();
    }
    if (threadIdx.x < NBLK) bsum[threadIdx.x] = sh[threadIdx.x] - v;
}
__global__ void scan_c(int* __restrict__ offs, const int* __restrict__ bsum,
                       int* __restrict__ cursor) {
    int gid = blockIdx.x * blockDim.x + threadIdx.x;
    if (gid < NN) {
        int o = offs[gid] + bsum[gid >> 10];
        offs[gid] = o;
        cursor[gid] = o;
    }
    if (gid == 0) offs[NN] = NE;
}
__global__ void place_edges(const int* __restrict__ src, const int* __restrict__ dst,
                            int* __restrict__ cursor, int* __restrict__ csrc) {
    int e = blockIdx.x * blockDim.x + threadIdx.x;
    if (e < NE) {
        int p = atomicAdd(cursor + dst[e], 1);
        csrc[p] = src[e];
    }
}

// ---------------- fp16 conversions -------------------------------------------
__global__ void cvt_x_h(const float4* __restrict__ in, uint4* __restrict__ out) {
    int i = blockIdx.x * blockDim.x + threadIdx.x;
    if (i >= NN_PAD * 16) return;
    uint4 u = make_uint4(0u, 0u, 0u, 0u);
    if (i < NN * 16) u = pack8h(in[2 * i], in[2 * i + 1]);
    out[i] = u;
}
__global__ void cvt_w_h(const float4* __restrict__ Wl, const float4* __restrict__ Wr,
                        uint4* __restrict__ out, int n8half) {
    int i = blockIdx.x * blockDim.x + threadIdx.x;
    if (i < n8half)
        out[i] = pack8h(Wl[2 * i], Wl[2 * i + 1]);
    else if (i < 2 * n8half) {
        int j = i - n8half;
        out[i] = pack8h(Wr[2 * j], Wr[2 * j + 1]);
    }
}
__global__ void cvt_y(const float4* __restrict__ in, uint4* __restrict__ out,
                      int n) {
    int i = blockIdx.x * blockDim.x + threadIdx.x;
    if (i >= n) return;
    out[i] = pack8h(in[2 * i], in[2 * i + 1]);
}

#define LDTH 24
#define STGW 132   // staging row stride in floats

// ---------------- FP16 GEMM N=256, Y written fp16 directly -------------------
// blockIdx.x==0 CTAs own cols [0,128) = Y entirely; ==1 own Z entirely.
// Y epilogue: store_matrix_sync -> smem staging (reuses pipeline smem after the
// final barrier), then cooperative fp16 pack with 512B-contiguous store
// instructions. Z epilogue identical to R12.
__global__ __launch_bounds__(256, 2) void h16gemm_y16(
    const __half* __restrict__ A, const __half* __restrict__ B,
    __half* __restrict__ YH, float* __restrict__ Z) {
    __shared__ __align__(16) char smraw[64 * STGW * 4];  // 33792 B
    __half (*As)[128][LDTH] = reinterpret_cast<__half(*)[128][LDTH]>(smraw);
    __half (*Bs)[128][LDTH] = reinterpret_cast<__half(*)[128][LDTH]>(smraw + 12288);
    float* stg = reinterpret_cast<float*>(smraw);

    const int tid = threadIdx.x;
    const int warp = tid >> 5;
    const int wm = warp & 3;
    const int wn = warp >> 2;
    const int bm0 = blockIdx.y * 128;
    const int bn0 = blockIdx.x * 128;

    wmma::fragment<wmma::accumulator, 16, 16, 16, float> acc[2][4];
    #pragma unroll
    for (int i = 0; i < 2; i++)
        #pragma unroll
        for (int j = 0; j < 4; j++)
            wmma::fill_fragment(acc[i][j], 0.0f);

    const int r = tid >> 1;
    const int c = (tid & 1) * 8;
    const __half* Ap = A + (size_t)(bm0 + r) * 128 + c;
    const __half* Bp = B + (size_t)(bn0 + r) * 128 + c;
    const uint32_t sA = smem_u32(&As[0][r][c]);
    const uint32_t sB = smem_u32(&Bs[0][r][c]);
    const uint32_t STG = 128 * LDTH * 2;

    CPA(sA, Ap); CPA(sB, Bp); CPC();

    #pragma unroll
    for (int t = 0; t < 8; t++) {
        const int cur = t & 1;
        if (t < 7) {
            const uint32_t so = ((t + 1) & 1) * STG;
            const int k0 = (t + 1) * 16;
            CPA(sA + so, Ap + k0);
            CPA(sB + so, Bp + k0);
            CPC();
            CPW(1);
        } else {
            CPW(0);
        }
        __syncthreads();

        wmma::fragment<wmma::matrix_a, 16, 16, 16, __half, wmma::row_major> af[2];
        wmma::fragment<wmma::matrix_b, 16, 16, 16, __half, wmma::col_major> bf[4];
        wmma::load_matrix_sync(af[0], &As[cur][wm * 32 + 0][0], LDTH);
        wmma::load_matrix_sync(af[1], &As[cur][wm * 32 + 16][0], LDTH);
        #pragma unroll
        for (int j = 0; j < 4; j++)
            wmma::load_matrix_sync(bf[j], &Bs[cur][wn * 64 + j * 16][0], LDTH);
        #pragma unroll
        for (int i = 0; i < 2; i++)
            #pragma unroll
            for (int j = 0; j < 4; j++)
                wmma::mma_sync(acc[i][j], af[i], bf[j], acc[i][j]);

        __syncthreads();   // all warps done with smem -> safe for next stage / staging
    }

    if (blockIdx.x == 0) {
        // ---- Y epilogue: fp16, coalesced ----
        #pragma unroll
        for (int i = 0; i < 2; i++) {
            #pragma unroll
            for (int j = 0; j < 4; j++)
                wmma::store_matrix_sync(stg + (wm * 16) * STGW + wn * 64 + j * 16,
                                        acc[i][j], STGW, wmma::mem_row_major);
            __syncthreads();
            #pragma unroll
            for (int k = 0; k < 4; k++) {
                int idx = tid + k * 256;           // 1024 uint4 total
                int srow = idx >> 4, c4 = idx & 15;
                int grow = bm0 + (srow >> 4) * 32 + i * 16 + (srow & 15);
                const float4* sp = (const float4*)(stg + srow * STGW + c4 * 8);
                ((uint4*)(YH + (size_t)grow * 128))[c4] = pack8h(sp[0], sp[1]);
            }
            if (i == 0) __syncthreads();
        }
    } else {
        // ---- Z epilogue: fp32, as R12 ----
        const int ccol = wn * 64;
        #pragma unroll
        for (int i = 0; i < 2; i++)
            #pragma unroll
            for (int j = 0; j < 4; j++) {
                int row0 = bm0 + wm * 32 + i * 16;
                wmma::store_matrix_sync(Z + (size_t)row0 * 128 + ccol + j * 16,
                                        acc[i][j], 128, wmma::mem_row_major);
            }
    }
}

// ---------------- FP16 GEMM (layer 2, N=128, fp32 Y/Z split) — proven R12 ----
__global__ __launch_bounds__(256, 2) void h16gemm(
    const __half* __restrict__ A, const __half* __restrict__ B,
    float* __restrict__ Y, float* __restrict__ Z, int N) {
    __shared__ __half As[2][128][LDTH];
    __shared__ __half Bs[2][128][LDTH];

    const int tid = threadIdx.x;
    const int warp = tid >> 5;
    const int wm = warp & 3;
    const int wn = warp >> 2;
    const int bm0 = blockIdx.y * 128;
    const int bn0 = blockIdx.x * 128;

    wmma::fragment<wmma::accumulator, 16, 16, 16, float> acc[2][4];
    #pragma unroll
    for (int i = 0; i < 2; i++)
        #pragma unroll
        for (int j = 0; j < 4; j++)
            wmma::fill_fragment(acc[i][j], 0.0f);

    const int r = tid >> 1;
    const int c = (tid & 1) * 8;
    const __half* Ap = A + (size_t)(bm0 + r) * 128 + c;
    const __half* Bp = B + (size_t)(bn0 + r) * 128 + c;
    const uint32_t sA = smem_u32(&As[0][r][c]);
    const uint32_t sB = smem_u32(&Bs[0][r][c]);
    const uint32_t STG = 128 * LDTH * 2;

    CPA(sA, Ap); CPA(sB, Bp); CPC();

    #pragma unroll
    for (int t = 0; t < 8; t++) {
        const int cur = t & 1;
        if (t < 7) {
            const uint32_t so = ((t + 1) & 1) * STG;
            const int k0 = (t + 1) * 16;
            CPA(sA + so, Ap + k0);
            CPA(sB + so, Bp + k0);
            CPC();
            CPW(1);
        } else {
            CPW(0);
        }
        __syncthreads();

        wmma::fragment<wmma::matrix_a, 16, 16, 16, __half, wmma::row_major> af[2];
        wmma::fragment<wmma::matrix_b, 16, 16, 16, __half, wmma::col_major> bf[4];
        wmma::load_matrix_sync(af[0], &As[cur][wm * 32 + 0][0], LDTH);
        wmma::load_matrix_sync(af[1], &As[cur][wm * 32 + 16][0], LDTH);
        #pragma unroll
        for (int j = 0; j < 4; j++)
            wmma::load_matrix_sync(bf[j], &Bs[cur][wn * 64 + j * 16][0], LDTH);
        #pragma unroll
        for (int i = 0; i < 2; i++)
            #pragma unroll
            for (int j = 0; j < 4; j++)
                wmma::mma_sync(acc[i][j], af[i], bf[j], acc[i][j]);

        __syncthreads();
    }

    const int halfN = N >> 1;
    const int slab0 = bn0 + wn * 64;
    float* Cb = (slab0 < halfN) ? Y : Z;
    const int ccol = (slab0 < halfN) ? slab0 : slab0 - halfN;
    #pragma unroll
    for (int i = 0; i < 2; i++)
        #pragma unroll
        for (int j = 0; j < 4; j++) {
            int row0 = bm0 + wm * 32 + i * 16;
            wmma::store_matrix_sync(Cb + (size_t)row0 * halfN + ccol + j * 16,
                                    acc[i][j], halfN, wmma::mem_row_major);
        }
}

// ---------------- fused aggregate + combine (R12, fp16 y gather) -------------
template <int HL, bool RELU>
__global__ void agg_combine(const uint4* __restrict__ yh4,
                            const float4* __restrict__ z4,
                            const int* __restrict__ csrc,
                            const int* __restrict__ offs,
                            const float* __restrict__ b,
                            uint4* __restrict__ outh,
                            float4* __restrict__ outf) {
    int gid = blockIdx.x * blockDim.x + threadIdx.x;
    int node = gid / HL;
    int lane = gid % HL;
    if (RELU) {
        if (node >= NN_PAD) return;
        if (node >= NN) {
            outh[(size_t)node * HL + lane] = make_uint4(0u, 0u, 0u, 0u);
            return;
        }
    } else {
        if (node >= NN) return;
    }

    int s = offs[node], e = offs[node + 1];
    float a[8] = {0.f, 0.f, 0.f, 0.f, 0.f, 0.f, 0.f, 0.f};
    int i = s;
    for (; i + 1 < e; i += 2) {
        uint4 u0 = yh4[(size_t)csrc[i] * HL + lane];
        uint4 u1 = yh4[(size_t)csrc[i + 1] * HL + lane];
        const __half2* p0 = (const __half2*)&u0;
        const __half2* p1 = (const __half2*)&u1;
        #pragma unroll
        for (int k = 0; k < 4; k++) {
            float2 f0 = __half22float2(p0[k]);
            float2 f1 = __half22float2(p1[k]);
            a[2 * k]     += f0.x + f1.x;
            a[2 * k + 1] += f0.y + f1.y;
        }
    }
    if (i < e) {
        uint4 u = yh4[(size_t)csrc[i] * HL + lane];
        const __half2* p = (const __half2*)&u;
        #pragma unroll
        for (int k = 0; k < 4; k++) {
            float2 f = __half22float2(p[k]);
            a[2 * k]     += f.x;
            a[2 * k + 1] += f.y;
        }
    }

    float inv = 1.0f / (float)max(e - s, 1);
    float4 z0 = z4[(size_t)node * 2 * HL + lane * 2 + 0];
    float4 z1 = z4[(size_t)node * 2 * HL + lane * 2 + 1];
    float4 bb0 = ((const float4*)b)[lane * 2 + 0];
    float4 bb1 = ((const float4*)b)[lane * 2 + 1];
    float4 o0, o1;
    o0.x = a[0] * inv + z0.x + bb0.x;
    o0.y = a[1] * inv + z0.y + bb0.y;
    o0.z = a[2] * inv + z0.z + bb0.z;
    o0.w = a[3] * inv + z0.w + bb0.w;
    o1.x = a[4] * inv + z1.x + bb1.x;
    o1.y = a[5] * inv + z1.y + bb1.y;
    o1.z = a[6] * inv + z1.z + bb1.z;
    o1.w = a[7] * inv + z1.w + bb1.w;
    if (RELU) {
        o0.x = fmaxf(o0.x, 0.f); o0.y = fmaxf(o0.y, 0.f);
        o0.z = fmaxf(o0.z, 0.f); o0.w = fmaxf(o0.w, 0.f);
        o1.x = fmaxf(o1.x, 0.f); o1.y = fmaxf(o1.y, 0.f);
        o1.z = fmaxf(o1.z, 0.f); o1.w = fmaxf(o1.w, 0.f);
        outh[(size_t)node * HL + lane] = pack8h(o0, o1);
    } else {
        outf[(size_t)node * 2 * HL + lane * 2 + 0] = o0;
        outf[(size_t)node * 2 * HL + lane * 2 + 1] = o1;
    }
}

// ---------------------------------------------------------------------------
extern "C" void kernel_launch(void* const* d_in, const int* in_sizes, int n_in,
                              void* d_out, int out_size) {
    const float* x   = (const float*)d_in[0];
    const int*   ei  = (const int*)d_in[1];
    const float* Wl0 = (const float*)d_in[2];
    const float* Wr0 = (const float*)d_in[3];
    const float* b0  = (const float*)d_in[4];
    const float* Wl1 = (const float*)d_in[5];
    const float* Wr1 = (const float*)d_in[6];
    const float* b1  = (const float*)d_in[7];
    const float* Wl2 = (const float*)d_in[8];
    const float* Wr2 = (const float*)d_in[9];
    const float* b2  = (const float*)d_in[10];
    float* out = (float*)d_out;

    const int* src = ei;
    const int* dst = ei + NE;

    float *y, *z;
    __half *xh, *yh, *h, *wc;
    int *cnt, *offs, *cursor, *csrc, *bsum;
    cudaGetSymbolAddress((void**)&xh,     g_x);
    cudaGetSymbolAddress((void**)&y,      g_y);
    cudaGetSymbolAddress((void**)&yh,     g_yh);
    cudaGetSymbolAddress((void**)&z,      g_z);
    cudaGetSymbolAddress((void**)&h,      g_h);
    cudaGetSymbolAddress((void**)&wc,     g_wcat);
    cudaGetSymbolAddress((void**)&cnt,    g_cnt);
    cudaGetSymbolAddress((void**)&offs,   g_offs);
    cudaGetSymbolAddress((void**)&cursor, g_cursor);
    cudaGetSymbolAddress((void**)&csrc,   g_csrc);
    cudaGetSymbolAddress((void**)&bsum,   g_bsum);
    __half* wc0 = wc;
    __half* wc1 = wc + 256 * 128;
    __half* wc2 = wc + 2 * 256 * 128;

    const int T = 256;
    dim3 gM(2, NN_PAD / 128);    // N = 256
    dim3 gM1(1, NN_PAD / 128);   // N = 128

    // Fork/join side stream (verified pattern).
    cudaStream_t s2;
    cudaEvent_t evFork, evJoin;
    cudaStreamCreateWithFlags(&s2, cudaStreamNonBlocking);
    cudaEventCreateWithFlags(&evFork, cudaEventDisableTiming);
    cudaEventCreateWithFlags(&evJoin, cudaEventDisableTiming);

    cudaEventRecord(evFork, 0);
    cudaStreamWaitEvent(s2, evFork, 0);

    // ---- main: fp16 prep + layer-0 GEMM (4th kernel launch for ncu) ----
    cvt_x_h<<<(NN_PAD * 16 + T - 1) / T, T>>>((const float4*)x, (uint4*)xh); // 1
    cvt_w_h<<<(2 * 2048 + T - 1) / T, T>>>((const float4*)Wl0,
                                           (const float4*)Wr0,
                                           (uint4*)wc0, 2048);               // 2
    zero_cnt<<<(NN + T - 1) / T, T, 0, s2>>>(cnt);                           // 3 (s2)
    h16gemm_y16<<<gM, T>>>(xh, wc0, yh, z);                                  // 4 <- ncu

    // ---- side stream: CSR build + remaining weight conversions ----
    count_deg<<<(NE + T - 1) / T, T, 0, s2>>>(dst, cnt);
    scan_a<<<NBLK, SCAN_B, 0, s2>>>(cnt, offs, bsum);
    scan_b<<<1, 128, 0, s2>>>(bsum);
    scan_c<<<(NN + T - 1) / T, T, 0, s2>>>(offs, bsum, cursor);
    place_edges<<<(NE + T - 1) / T, T, 0, s2>>>(src, dst, cursor, csrc);
    cvt_w_h<<<(2 * 2048 + T - 1) / T, T, 0, s2>>>((const float4*)Wl1,
                                                  (const float4*)Wr1,
                                                  (uint4*)wc1, 2048);
    cvt_w_h<<<(2 * 1024 + T - 1) / T, T, 0, s2>>>((const float4*)Wl2,
                                                  (const float4*)Wr2,
                                                  (uint4*)wc2, 1024);
    cudaEventRecord(evJoin, s2);
    cudaStreamWaitEvent(0, evJoin, 0);

    // ---- layer 0 combine (writes fp16 h) ----
    agg_combine<16, true><<<(NN_PAD * 16 + T - 1) / T, T>>>(
        (const uint4*)yh, (const float4*)z, csrc, offs, b0, (uint4*)h, nullptr);

    // ---- layer 1 ----
    h16gemm_y16<<<gM, T>>>(h, wc1, yh, z);
    agg_combine<16, true><<<(NN_PAD * 16 + T - 1) / T, T>>>(
        (const uint4*)yh, (const float4*)z, csrc, offs, b1, (uint4*)h, nullptr);

    // ---- layer 2 (d_out = 64, no relu, fp32 out) ----
    h16gemm<<<gM1, T>>>(h, wc2, y, z, 128);
    cvt_y<<<(NN * 8 + T - 1) / T, T>>>((const float4*)y, (uint4*)yh, NN * 8);
    agg_combine<8, false><<<(NN * 8 + T - 1) / T, T>>>(
        (const uint4*)yh, (const float4*)z, csrc, offs, b2, nullptr, (float4*)out);
}

// round 15
// speedup vs baseline: 1.1126x; 1.0470x over previous
#include <cuda_runtime.h>
#include <mma.h>
#include <cuda_fp16.h>
#include <cstddef>
#include <cstdint>

using namespace nvcuda;

#define NN 100000
#define NN_PAD 100096            // 782 * 128
#define NE 1600000
#define SCAN_B 1024
#define NBLK ((NN + SCAN_B - 1) / SCAN_B)   // 98

// ---------------- scratch ---------------------------------------------------
__device__ __half g_x[(size_t)NN_PAD * 128];   // x in fp16 (padded, zeroed)
__device__ __half g_yh[(size_t)NN_PAD * 128];  // y fp16 (gathered over edges)
__device__ __half g_zh[(size_t)NN_PAD * 128];  // z fp16 (streamed per node)
__device__ __half g_h[(size_t)NN_PAD * 128];   // activations fp16 (padded)
__device__ __half g_wcat[3][256 * 128];        // fp16 [Wl ; Wr] per layer
__device__ int    g_cnt[NN];
__device__ int    g_offs[NN + 1];
__device__ int    g_cursor[NN];
__device__ int    g_csrc[NE];
__device__ int    g_bsum[NBLK];

// ---------------- helpers ---------------------------------------------------
__device__ __forceinline__ uint4 pack8h(float4 f0, float4 f1) {
    union { uint4 u; __half2 h[4]; } P;
    P.h[0] = __floats2half2_rn(f0.x, f0.y);
    P.h[1] = __floats2half2_rn(f0.z, f0.w);
    P.h[2] = __floats2half2_rn(f1.x, f1.y);
    P.h[3] = __floats2half2_rn(f1.z, f1.w);
    return P.u;
}
__device__ __forceinline__ uint32_t smem_u32(const void* p) {
    return (uint32_t)__cvta_generic_to_shared(p);
}
#define CPA(dst, src) \
    asm volatile("cp.async.cg.shared.global [%0], [%1], 16;" :: "r"(dst), "l"(src))
#define CPC() asm volatile("cp.async.commit_group;")
#define CPW(n) asm volatile("cp.async.wait_group %0;" :: "n"(n))

// ---------------- CSR build -------------------------------------------------
__global__ void count_deg(const int* __restrict__ dst, int* __restrict__ cnt) {
    int e = blockIdx.x * blockDim.x + threadIdx.x;
    if (e < NE) atomicAdd(cnt + dst[e], 1);
}
__global__ void zero_cnt(int* __restrict__ cnt) {
    int i = blockIdx.x * blockDim.x + threadIdx.x;
    if (i < NN) cnt[i] = 0;
}
__global__ void scan_a(const int* __restrict__ cnt, int* __restrict__ offs,
                       int* __restrict__ bsum) {
    __shared__ int sh[SCAN_B];
    int gid = blockIdx.x * SCAN_B + threadIdx.x;
    int v = (gid < NN) ? cnt[gid] : 0;
    sh[threadIdx.x] = v;
    __syncthreads();
    for (int d = 1; d < SCAN_B; d <<= 1) {
        int t = (threadIdx.x >= d) ? sh[threadIdx.x - d] : 0;
        __syncthreads();
        sh[threadIdx.x] += t;
        __syncthreads();
    }
    if (gid < NN) offs[gid] = sh[threadIdx.x] - v;
    if (threadIdx.x == SCAN_B - 1) bsum[blockIdx.x] = sh[threadIdx.x];
}
__global__ void scan_b(int* __restrict__ bsum) {
    __shared__ int sh[128];
    int v = (threadIdx.x < NBLK) ? bsum[threadIdx.x] : 0;
    sh[threadIdx.x] = v;
    __syncthreads();
    for (int d = 1; d < 128; d <<= 1) {
        int t = (threadIdx.x >= d) ? sh[threadIdx.x - d] : 0;
        __syncthreads();
        sh[threadIdx.x] += t;
        __syncthreads();
    }
    if (threadIdx.x < NBLK) bsum[threadIdx.x] = sh[threadIdx.x] - v;
}
__global__ void scan_c(int* __restrict__ offs, const int* __restrict__ bsum,
                       int* __restrict__ cursor) {
    int gid = blockIdx.x * blockDim.x + threadIdx.x;
    if (gid < NN) {
        int o = offs[gid] + bsum[gid >> 10];
        offs[gid] = o;
        cursor[gid] = o;
    }
    if (gid == 0) offs[NN] = NE;
}
__global__ void place_edges(const int* __restrict__ src, const int* __restrict__ dst,
                            int* __restrict__ cursor, int* __restrict__ csrc) {
    int e = blockIdx.x * blockDim.x + threadIdx.x;
    if (e < NE) {
        int p = atomicAdd(cursor + dst[e], 1);
        csrc[p] = src[e];
    }
}

// ---------------- fp16 conversions -------------------------------------------
__global__ void cvt_x_h(const float4* __restrict__ in, uint4* __restrict__ out) {
    int i = blockIdx.x * blockDim.x + threadIdx.x;
    if (i >= NN_PAD * 16) return;
    uint4 u = make_uint4(0u, 0u, 0u, 0u);
    if (i < NN * 16) u = pack8h(in[2 * i], in[2 * i + 1]);
    out[i] = u;
}
__global__ void cvt_w_h(const float4* __restrict__ Wl, const float4* __restrict__ Wr,
                        uint4* __restrict__ out, int n8half) {
    int i = blockIdx.x * blockDim.x + threadIdx.x;
    if (i < n8half)
        out[i] = pack8h(Wl[2 * i], Wl[2 * i + 1]);
    else if (i < 2 * n8half) {
        int j = i - n8half;
        out[i] = pack8h(Wr[2 * j], Wr[2 * j + 1]);
    }
}

#define LDTH 24
#define STGW 132   // staging row stride in floats

// ---------------- FP16 GEMM, fp16 Y/Z outputs (unified N=256 / N=128) --------
// [Y|Z][M, N/2 fp16 each] = A[M,128] * B[N,128]^T, B = [Wl;Wr] concat.
// Mainloop = proven R12 kernel. Epilogue: store_matrix_sync -> smem staging
// (reuses pipeline smem after final barrier), cooperative fp16 pack with
// 512B-contiguous stores; each 8-col group routes to YH or ZH by global col.
__global__ __launch_bounds__(256, 2) void h16gemm_hh(
    const __half* __restrict__ A, const __half* __restrict__ B,
    __half* __restrict__ YH, __half* __restrict__ ZH, int N) {
    __shared__ __align__(16) char smraw[64 * STGW * 4];  // 33792 B
    __half (*As)[128][LDTH] = reinterpret_cast<__half(*)[128][LDTH]>(smraw);
    __half (*Bs)[128][LDTH] = reinterpret_cast<__half(*)[128][LDTH]>(smraw + 12288);
    float* stg = reinterpret_cast<float*>(smraw);

    const int tid = threadIdx.x;
    const int warp = tid >> 5;
    const int wm = warp & 3;
    const int wn = warp >> 2;
    const int bm0 = blockIdx.y * 128;
    const int bn0 = blockIdx.x * 128;

    wmma::fragment<wmma::accumulator, 16, 16, 16, float> acc[2][4];
    #pragma unroll
    for (int i = 0; i < 2; i++)
        #pragma unroll
        for (int j = 0; j < 4; j++)
            wmma::fill_fragment(acc[i][j], 0.0f);

    const int r = tid >> 1;
    const int c = (tid & 1) * 8;
    const __half* Ap = A + (size_t)(bm0 + r) * 128 + c;
    const __half* Bp = B + (size_t)(bn0 + r) * 128 + c;
    const uint32_t sA = smem_u32(&As[0][r][c]);
    const uint32_t sB = smem_u32(&Bs[0][r][c]);
    const uint32_t STG = 128 * LDTH * 2;

    CPA(sA, Ap); CPA(sB, Bp); CPC();

    #pragma unroll
    for (int t = 0; t < 8; t++) {
        const int cur = t & 1;
        if (t < 7) {
            const uint32_t so = ((t + 1) & 1) * STG;
            const int k0 = (t + 1) * 16;
            CPA(sA + so, Ap + k0);
            CPA(sB + so, Bp + k0);
            CPC();
            CPW(1);
        } else {
            CPW(0);
        }
        __syncthreads();

        wmma::fragment<wmma::matrix_a, 16, 16, 16, __half, wmma::row_major> af[2];
        wmma::fragment<wmma::matrix_b, 16, 16, 16, __half, wmma::col_major> bf[4];
        wmma::load_matrix_sync(af[0], &As[cur][wm * 32 + 0][0], LDTH);
        wmma::load_matrix_sync(af[1], &As[cur][wm * 32 + 16][0], LDTH);
        #pragma unroll
        for (int j = 0; j < 4; j++)
            wmma::load_matrix_sync(bf[j], &Bs[cur][wn * 64 + j * 16][0], LDTH);
        #pragma unroll
        for (int i = 0; i < 2; i++)
            #pragma unroll
            for (int j = 0; j < 4; j++)
                wmma::mma_sync(acc[i][j], af[i], bf[j], acc[i][j]);

        __syncthreads();   // smem free after this -> next stage / staging reuse
    }

    const int halfN = N >> 1;
    #pragma unroll
    for (int i = 0; i < 2; i++) {
        #pragma unroll
        for (int j = 0; j < 4; j++)
            wmma::store_matrix_sync(stg + (wm * 16) * STGW + wn * 64 + j * 16,
                                    acc[i][j], STGW, wmma::mem_row_major);
        __syncthreads();
        #pragma unroll
        for (int k = 0; k < 4; k++) {
            int idx = tid + k * 256;           // 1024 uint4 total (64 x 128)
            int srow = idx >> 4, c4 = idx & 15;
            int grow = bm0 + (srow >> 4) * 32 + i * 16 + (srow & 15);
            const float4* sp = (const float4*)(stg + srow * STGW + c4 * 8);
            uint4 v = pack8h(sp[0], sp[1]);
            int gcol = bn0 + c4 * 8;
            if (gcol < halfN)
                *((uint4*)(YH + (size_t)grow * halfN) + (gcol >> 3)) = v;
            else
                *((uint4*)(ZH + (size_t)grow * halfN) + ((gcol - halfN) >> 3)) = v;
        }
        if (i == 0) __syncthreads();
    }
}

// ---------------- fused aggregate + combine (fp16 y gather + fp16 z) ---------
// out = [relu]( mean_{j in CSR[i]} y_j + z_i + b ); fp32 accumulate.
// HL lanes per node, 8 cols per lane. RELU layers write fp16 h; final fp32.
template <int HL, bool RELU>
__global__ void agg_combine(const uint4* __restrict__ yh4,
                            const uint4* __restrict__ zh4,
                            const int* __restrict__ csrc,
                            const int* __restrict__ offs,
                            const float* __restrict__ b,
                            uint4* __restrict__ outh,
                            float4* __restrict__ outf) {
    int gid = blockIdx.x * blockDim.x + threadIdx.x;
    int node = gid / HL;
    int lane = gid % HL;
    if (RELU) {
        if (node >= NN_PAD) return;
        if (node >= NN) {
            outh[(size_t)node * HL + lane] = make_uint4(0u, 0u, 0u, 0u);
            return;
        }
    } else {
        if (node >= NN) return;
    }

    int s = offs[node], e = offs[node + 1];
    float a[8] = {0.f, 0.f, 0.f, 0.f, 0.f, 0.f, 0.f, 0.f};
    int i = s;
    for (; i + 1 < e; i += 2) {
        uint4 u0 = yh4[(size_t)csrc[i] * HL + lane];
        uint4 u1 = yh4[(size_t)csrc[i + 1] * HL + lane];
        const __half2* p0 = (const __half2*)&u0;
        const __half2* p1 = (const __half2*)&u1;
        #pragma unroll
        for (int k = 0; k < 4; k++) {
            float2 f0 = __half22float2(p0[k]);
            float2 f1 = __half22float2(p1[k]);
            a[2 * k]     += f0.x + f1.x;
            a[2 * k + 1] += f0.y + f1.y;
        }
    }
    if (i < e) {
        uint4 u = yh4[(size_t)csrc[i] * HL + lane];
        const __half2* p = (const __half2*)&u;
        #pragma unroll
        for (int k = 0; k < 4; k++) {
            float2 f = __half22float2(p[k]);
            a[2 * k]     += f.x;
            a[2 * k + 1] += f.y;
        }
    }

    float inv = 1.0f / (float)max(e - s, 1);
    uint4 uz = zh4[(size_t)node * HL + lane];
    const __half2* pz = (const __half2*)&uz;
    float2 zv[4];
    #pragma unroll
    for (int k = 0; k < 4; k++) zv[k] = __half22float2(pz[k]);
    float4 bb0 = ((const float4*)b)[lane * 2 + 0];
    float4 bb1 = ((const float4*)b)[lane * 2 + 1];
    float4 o0, o1;
    o0.x = a[0] * inv + zv[0].x + bb0.x;
    o0.y = a[1] * inv + zv[0].y + bb0.y;
    o0.z = a[2] * inv + zv[1].x + bb0.z;
    o0.w = a[3] * inv + zv[1].y + bb0.w;
    o1.x = a[4] * inv + zv[2].x + bb1.x;
    o1.y = a[5] * inv + zv[2].y + bb1.y;
    o1.z = a[6] * inv + zv[3].x + bb1.z;
    o1.w = a[7] * inv + zv[3].y + bb1.w;
    if (RELU) {
        o0.x = fmaxf(o0.x, 0.f); o0.y = fmaxf(o0.y, 0.f);
        o0.z = fmaxf(o0.z, 0.f); o0.w = fmaxf(o0.w, 0.f);
        o1.x = fmaxf(o1.x, 0.f); o1.y = fmaxf(o1.y, 0.f);
        o1.z = fmaxf(o1.z, 0.f); o1.w = fmaxf(o1.w, 0.f);
        outh[(size_t)node * HL + lane] = pack8h(o0, o1);
    } else {
        outf[(size_t)node * 2 * HL + lane * 2 + 0] = o0;
        outf[(size_t)node * 2 * HL + lane * 2 + 1] = o1;
    }
}

// ---------------------------------------------------------------------------
extern "C" void kernel_launch(void* const* d_in, const int* in_sizes, int n_in,
                              void* d_out, int out_size) {
    const float* x   = (const float*)d_in[0];
    const int*   ei  = (const int*)d_in[1];
    const float* Wl0 = (const float*)d_in[2];
    const float* Wr0 = (const float*)d_in[3];
    const float* b0  = (const float*)d_in[4];
    const float* Wl1 = (const float*)d_in[5];
    const float* Wr1 = (const float*)d_in[6];
    const float* b1  = (const float*)d_in[7];
    const float* Wl2 = (const float*)d_in[8];
    const float* Wr2 = (const float*)d_in[9];
    const float* b2  = (const float*)d_in[10];
    float* out = (float*)d_out;

    const int* src = ei;
    const int* dst = ei + NE;

    __half *xh, *yh, *zh, *h, *wc;
    int *cnt, *offs, *cursor, *csrc, *bsum;
    cudaGetSymbolAddress((void**)&xh,     g_x);
    cudaGetSymbolAddress((void**)&yh,     g_yh);
    cudaGetSymbolAddress((void**)&zh,     g_zh);
    cudaGetSymbolAddress((void**)&h,      g_h);
    cudaGetSymbolAddress((void**)&wc,     g_wcat);
    cudaGetSymbolAddress((void**)&cnt,    g_cnt);
    cudaGetSymbolAddress((void**)&offs,   g_offs);
    cudaGetSymbolAddress((void**)&cursor, g_cursor);
    cudaGetSymbolAddress((void**)&csrc,   g_csrc);
    cudaGetSymbolAddress((void**)&bsum,   g_bsum);
    __half* wc0 = wc;
    __half* wc1 = wc + 256 * 128;
    __half* wc2 = wc + 2 * 256 * 128;

    const int T = 256;
    dim3 gM(2, NN_PAD / 128);    // N = 256
    dim3 gM1(1, NN_PAD / 128);   // N = 128

    // Fork/join side stream (verified pattern).
    cudaStream_t s2;
    cudaEvent_t evFork, evJoin;
    cudaStreamCreateWithFlags(&s2, cudaStreamNonBlocking);
    cudaEventCreateWithFlags(&evFork, cudaEventDisableTiming);
    cudaEventCreateWithFlags(&evJoin, cudaEventDisableTiming);

    cudaEventRecord(evFork, 0);
    cudaStreamWaitEvent(s2, evFork, 0);

    // ---- main: fp16 prep + layer-0 GEMM (4th kernel launch for ncu) ----
    cvt_x_h<<<(NN_PAD * 16 + T - 1) / T, T>>>((const float4*)x, (uint4*)xh); // 1
    cvt_w_h<<<(2 * 2048 + T - 1) / T, T>>>((const float4*)Wl0,
                                           (const float4*)Wr0,
                                           (uint4*)wc0, 2048);               // 2
    zero_cnt<<<(NN + T - 1) / T, T, 0, s2>>>(cnt);                           // 3 (s2)
    h16gemm_hh<<<gM, T>>>(xh, wc0, yh, zh, 256);                             // 4 <- ncu

    // ---- side stream: CSR build + remaining weight conversions ----
    count_deg<<<(NE + T - 1) / T, T, 0, s2>>>(dst, cnt);
    scan_a<<<NBLK, SCAN_B, 0, s2>>>(cnt, offs, bsum);
    scan_b<<<1, 128, 0, s2>>>(bsum);
    scan_c<<<(NN + T - 1) / T, T, 0, s2>>>(offs, bsum, cursor);
    place_edges<<<(NE + T - 1) / T, T, 0, s2>>>(src, dst, cursor, csrc);
    cvt_w_h<<<(2 * 2048 + T - 1) / T, T, 0, s2>>>((const float4*)Wl1,
                                                  (const float4*)Wr1,
                                                  (uint4*)wc1, 2048);
    cvt_w_h<<<(2 * 1024 + T - 1) / T, T, 0, s2>>>((const float4*)Wl2,
                                                  (const float4*)Wr2,
                                                  (uint4*)wc2, 1024);
    cudaEventRecord(evJoin, s2);
    cudaStreamWaitEvent(0, evJoin, 0);

    // ---- layer 0 combine (writes fp16 h) ----
    agg_combine<16, true><<<(NN_PAD * 16 + T - 1) / T, T>>>(
        (const uint4*)yh, (const uint4*)zh, csrc, offs, b0, (uint4*)h, nullptr);

    // ---- layer 1 ----
    h16gemm_hh<<<gM, T>>>(h, wc1, yh, zh, 256);
    agg_combine<16, true><<<(NN_PAD * 16 + T - 1) / T, T>>>(
        (const uint4*)yh, (const uint4*)zh, csrc, offs, b1, (uint4*)h, nullptr);

    // ---- layer 2 (d_out = 64, no relu, fp32 out) ----
    h16gemm_hh<<<gM1, T>>>(h, wc2, yh, zh, 128);
    agg_combine<8, false><<<(NN * 8 + T - 1) / T, T>>>(
        (const uint4*)yh, (const uint4*)zh, csrc, offs, b2, nullptr, (float4*)out);
}

// round 16
// speedup vs baseline: 1.1235x; 1.0098x over previous
#include <cuda_runtime.h>
#include <mma.h>
#include <cuda_fp16.h>
#include <cstddef>
#include <cstdint>

using namespace nvcuda;

#define NN 100000
#define NN_PAD 100096            // 782 * 128
#define NE 1600000
#define SCAN_B 1024
#define NBLK ((NN + SCAN_B - 1) / SCAN_B)   // 98

// ---------------- scratch ---------------------------------------------------
__device__ __half g_x[(size_t)NN_PAD * 128];   // x in fp16 (padded, zeroed)
__device__ __half g_yh[(size_t)NN_PAD * 128];  // y fp16 (gathered over edges)
__device__ __half g_zh[(size_t)NN_PAD * 128];  // z fp16 (streamed per node)
__device__ __half g_h[(size_t)NN_PAD * 128];   // activations fp16 (padded)
__device__ __half g_wcat[3][256 * 128];        // fp16 [Wl ; Wr] per layer
__device__ int    g_cnt[NN];
__device__ int    g_offs[NN + 1];
__device__ int    g_cursor[NN];
__device__ int    g_csrc[NE];
__device__ int    g_bsum[NBLK];

// ---------------- helpers ---------------------------------------------------
__device__ __forceinline__ uint4 pack8h(float4 f0, float4 f1) {
    union { uint4 u; __half2 h[4]; } P;
    P.h[0] = __floats2half2_rn(f0.x, f0.y);
    P.h[1] = __floats2half2_rn(f0.z, f0.w);
    P.h[2] = __floats2half2_rn(f1.x, f1.y);
    P.h[3] = __floats2half2_rn(f1.z, f1.w);
    return P.u;
}
__device__ __forceinline__ uint32_t smem_u32(const void* p) {
    return (uint32_t)__cvta_generic_to_shared(p);
}
#define CPA(dst, src) \
    asm volatile("cp.async.cg.shared.global [%0], [%1], 16;" :: "r"(dst), "l"(src))
#define CPC() asm volatile("cp.async.commit_group;")
#define CPW(n) asm volatile("cp.async.wait_group %0;" :: "n"(n))

// ---------------- CSR build -------------------------------------------------
__global__ void count_deg(const int* __restrict__ dst, int* __restrict__ cnt) {
    int e = blockIdx.x * blockDim.x + threadIdx.x;
    if (e < NE) atomicAdd(cnt + dst[e], 1);
}
__global__ void zero_cnt(int* __restrict__ cnt) {
    int i = blockIdx.x * blockDim.x + threadIdx.x;
    if (i < NN) cnt[i] = 0;
}
__global__ void scan_a(const int* __restrict__ cnt, int* __restrict__ offs,
                       int* __restrict__ bsum) {
    __shared__ int sh[SCAN_B];
    int gid = blockIdx.x * SCAN_B + threadIdx.x;
    int v = (gid < NN) ? cnt[gid] : 0;
    sh[threadIdx.x] = v;
    __syncthreads();
    for (int d = 1; d < SCAN_B; d <<= 1) {
        int t = (threadIdx.x >= d) ? sh[threadIdx.x - d] : 0;
        __syncthreads();
        sh[threadIdx.x] += t;
        __syncthreads();
    }
    if (gid < NN) offs[gid] = sh[threadIdx.x] - v;
    if (threadIdx.x == SCAN_B - 1) bsum[blockIdx.x] = sh[threadIdx.x];
}
__global__ void scan_b(int* __restrict__ bsum) {
    __shared__ int sh[128];
    int v = (threadIdx.x < NBLK) ? bsum[threadIdx.x] : 0;
    sh[threadIdx.x] = v;
    __syncthreads();
    for (int d = 1; d < 128; d <<= 1) {
        int t = (threadIdx.x >= d) ? sh[threadIdx.x - d] : 0;
        __syncthreads();
        sh[threadIdx.x] += t;
        __syncthreads();
    }
    if (threadIdx.x < NBLK) bsum[threadIdx.x] = sh[threadIdx.x] - v;
}
__global__ void scan_c(int* __restrict__ offs, const int* __restrict__ bsum,
                       int* __restrict__ cursor) {
    int gid = blockIdx.x * blockDim.x + threadIdx.x;
    if (gid < NN) {
        int o = offs[gid] + bsum[gid >> 10];
        offs[gid] = o;
        cursor[gid] = o;
    }
    if (gid == 0) offs[NN] = NE;
}
__global__ void place_edges(const int* __restrict__ src, const int* __restrict__ dst,
                            int* __restrict__ cursor, int* __restrict__ csrc) {
    int e = blockIdx.x * blockDim.x + threadIdx.x;
    if (e < NE) {
        int p = atomicAdd(cursor + dst[e], 1);
        csrc[p] = src[e];
    }
}

// ---------------- fp16 conversions -------------------------------------------
__global__ void cvt_x_h(const float4* __restrict__ in, uint4* __restrict__ out) {
    int i = blockIdx.x * blockDim.x + threadIdx.x;
    if (i >= NN_PAD * 16) return;
    uint4 u = make_uint4(0u, 0u, 0u, 0u);
    if (i < NN * 16) u = pack8h(in[2 * i], in[2 * i + 1]);
    out[i] = u;
}
__global__ void cvt_w_h(const float4* __restrict__ Wl, const float4* __restrict__ Wr,
                        uint4* __restrict__ out, int n8half) {
    int i = blockIdx.x * blockDim.x + threadIdx.x;
    if (i < n8half)
        out[i] = pack8h(Wl[2 * i], Wl[2 * i + 1]);
    else if (i < 2 * n8half) {
        int j = i - n8half;
        out[i] = pack8h(Wr[2 * j], Wr[2 * j + 1]);
    }
}

#define LDTH 24
#define STGW 132    // staging row stride in floats
#define STGB 6144   // one stage of one matrix: 128 * 24 halves * 2 B

// ---------------- FP16 GEMM, fp16 Y/Z outputs, 3-stage single-barrier --------
// [Y|Z][M, N/2 fp16 each] = A[M,128] * B[N,128]^T, B = [Wl;Wr] concat.
// 3-stage cp.async pipeline, ONE __syncthreads per k-iter:
//   iter t: wait_group(1) (group t done) -> barrier -> compute stage t%3
//           -> issue stage (t+2)%3 (== stage (t-1)%3, safe: every warp past
//              the barrier finished reading it at iter t-1) -> commit.
// Epilogue: smem staging + coalesced fp16 pack (proven R14/R15 pattern).
__global__ __launch_bounds__(256, 2) void h16gemm_hh(
    const __half* __restrict__ A, const __half* __restrict__ B,
    __half* __restrict__ YH, __half* __restrict__ ZH, int N) {
    __shared__ __align__(16) char smraw[6 * STGB];   // As[3] | Bs[3] = 36864 B
    __half (*As)[128][LDTH] = reinterpret_cast<__half(*)[128][LDTH]>(smraw);
    __half (*Bs)[128][LDTH] = reinterpret_cast<__half(*)[128][LDTH]>(smraw + 3 * STGB);
    float* stg = reinterpret_cast<float*>(smraw);    // 33792 B <= 36864 B

    const int tid = threadIdx.x;
    const int warp = tid >> 5;
    const int wm = warp & 3;
    const int wn = warp >> 2;
    const int bm0 = blockIdx.y * 128;
    const int bn0 = blockIdx.x * 128;

    wmma::fragment<wmma::accumulator, 16, 16, 16, float> acc[2][4];
    #pragma unroll
    for (int i = 0; i < 2; i++)
        #pragma unroll
        for (int j = 0; j < 4; j++)
            wmma::fill_fragment(acc[i][j], 0.0f);

    const int r = tid >> 1;
    const int c = (tid & 1) * 8;
    const __half* Ap = A + (size_t)(bm0 + r) * 128 + c;
    const __half* Bp = B + (size_t)(bn0 + r) * 128 + c;
    const uint32_t sA = smem_u32(&As[0][r][c]);
    const uint32_t sB = smem_u32(&Bs[0][r][c]);

    // Prologue: stages 0 and 1 (groups g0, g1).
    CPA(sA, Ap); CPA(sB, Bp); CPC();
    CPA(sA + STGB, Ap + 16); CPA(sB + STGB, Bp + 16); CPC();

    #pragma unroll
    for (int t = 0; t < 8; t++) {
        CPW(1);            // group t complete (only g_{t+1} may be in flight)
        __syncthreads();   // visibility + all warps done reading stage (t-1)%3

        const int st = t % 3;
        wmma::fragment<wmma::matrix_a, 16, 16, 16, __half, wmma::row_major> af[2];
        wmma::fragment<wmma::matrix_b, 16, 16, 16, __half, wmma::col_major> bf[4];
        wmma::load_matrix_sync(af[0], &As[st][wm * 32 + 0][0], LDTH);
        wmma::load_matrix_sync(af[1], &As[st][wm * 32 + 16][0], LDTH);
        #pragma unroll
        for (int j = 0; j < 4; j++)
            wmma::load_matrix_sync(bf[j], &Bs[st][wn * 64 + j * 16][0], LDTH);
        #pragma unroll
        for (int i = 0; i < 2; i++)
            #pragma unroll
            for (int j = 0; j < 4; j++)
                wmma::mma_sync(acc[i][j], af[i], bf[j], acc[i][j]);

        if (t < 6) {       // issue stage (t+2)%3 for k-chunk t+2
            const uint32_t so = (uint32_t)((t + 2) % 3) * STGB;
            const int k0 = (t + 2) * 16;
            CPA(sA + so, Ap + k0);
            CPA(sB + so, Bp + k0);
        }
        CPC();             // commit (possibly empty) to keep group counts aligned
    }
    __syncthreads();       // all LDSM reads done before staging reuses smem

    const int halfN = N >> 1;
    #pragma unroll
    for (int i = 0; i < 2; i++) {
        #pragma unroll
        for (int j = 0; j < 4; j++)
            wmma::store_matrix_sync(stg + (wm * 16) * STGW + wn * 64 + j * 16,
                                    acc[i][j], STGW, wmma::mem_row_major);
        __syncthreads();
        #pragma unroll
        for (int k = 0; k < 4; k++) {
            int idx = tid + k * 256;           // 1024 uint4 total (64 x 128)
            int srow = idx >> 4, c4 = idx & 15;
            int grow = bm0 + (srow >> 4) * 32 + i * 16 + (srow & 15);
            const float4* sp = (const float4*)(stg + srow * STGW + c4 * 8);
            uint4 v = pack8h(sp[0], sp[1]);
            int gcol = bn0 + c4 * 8;
            if (gcol < halfN)
                *((uint4*)(YH + (size_t)grow * halfN) + (gcol >> 3)) = v;
            else
                *((uint4*)(ZH + (size_t)grow * halfN) + ((gcol - halfN) >> 3)) = v;
        }
        if (i == 0) __syncthreads();
    }
}

// ---------------- fused aggregate + combine (fp16 y gather + fp16 z) ---------
template <int HL, bool RELU>
__global__ void agg_combine(const uint4* __restrict__ yh4,
                            const uint4* __restrict__ zh4,
                            const int* __restrict__ csrc,
                            const int* __restrict__ offs,
                            const float* __restrict__ b,
                            uint4* __restrict__ outh,
                            float4* __restrict__ outf) {
    int gid = blockIdx.x * blockDim.x + threadIdx.x;
    int node = gid / HL;
    int lane = gid % HL;
    if (RELU) {
        if (node >= NN_PAD) return;
        if (node >= NN) {
            outh[(size_t)node * HL + lane] = make_uint4(0u, 0u, 0u, 0u);
            return;
        }
    } else {
        if (node >= NN) return;
    }

    int s = offs[node], e = offs[node + 1];
    float a[8] = {0.f, 0.f, 0.f, 0.f, 0.f, 0.f, 0.f, 0.f};
    int i = s;
    for (; i + 1 < e; i += 2) {
        uint4 u0 = yh4[(size_t)csrc[i] * HL + lane];
        uint4 u1 = yh4[(size_t)csrc[i + 1] * HL + lane];
        const __half2* p0 = (const __half2*)&u0;
        const __half2* p1 = (const __half2*)&u1;
        #pragma unroll
        for (int k = 0; k < 4; k++) {
            float2 f0 = __half22float2(p0[k]);
            float2 f1 = __half22float2(p1[k]);
            a[2 * k]     += f0.x + f1.x;
            a[2 * k + 1] += f0.y + f1.y;
        }
    }
    if (i < e) {
        uint4 u = yh4[(size_t)csrc[i] * HL + lane];
        const __half2* p = (const __half2*)&u;
        #pragma unroll
        for (int k = 0; k < 4; k++) {
            float2 f = __half22float2(p[k]);
            a[2 * k]     += f.x;
            a[2 * k + 1] += f.y;
        }
    }

    float inv = 1.0f / (float)max(e - s, 1);
    uint4 uz = zh4[(size_t)node * HL + lane];
    const __half2* pz = (const __half2*)&uz;
    float2 zv[4];
    #pragma unroll
    for (int k = 0; k < 4; k++) zv[k] = __half22float2(pz[k]);
    float4 bb0 = ((const float4*)b)[lane * 2 + 0];
    float4 bb1 = ((const float4*)b)[lane * 2 + 1];
    float4 o0, o1;
    o0.x = a[0] * inv + zv[0].x + bb0.x;
    o0.y = a[1] * inv + zv[0].y + bb0.y;
    o0.z = a[2] * inv + zv[1].x + bb0.z;
    o0.w = a[3] * inv + zv[1].y + bb0.w;
    o1.x = a[4] * inv + zv[2].x + bb1.x;
    o1.y = a[5] * inv + zv[2].y + bb1.y;
    o1.z = a[6] * inv + zv[3].x + bb1.z;
    o1.w = a[7] * inv + zv[3].y + bb1.w;
    if (RELU) {
        o0.x = fmaxf(o0.x, 0.f); o0.y = fmaxf(o0.y, 0.f);
        o0.z = fmaxf(o0.z, 0.f); o0.w = fmaxf(o0.w, 0.f);
        o1.x = fmaxf(o1.x, 0.f); o1.y = fmaxf(o1.y, 0.f);
        o1.z = fmaxf(o1.z, 0.f); o1.w = fmaxf(o1.w, 0.f);
        outh[(size_t)node * HL + lane] = pack8h(o0, o1);
    } else {
        outf[(size_t)node * 2 * HL + lane * 2 + 0] = o0;
        outf[(size_t)node * 2 * HL + lane * 2 + 1] = o1;
    }
}

// ---------------------------------------------------------------------------
extern "C" void kernel_launch(void* const* d_in, const int* in_sizes, int n_in,
                              void* d_out, int out_size) {
    const float* x   = (const float*)d_in[0];
    const int*   ei  = (const int*)d_in[1];
    const float* Wl0 = (const float*)d_in[2];
    const float* Wr0 = (const float*)d_in[3];
    const float* b0  = (const float*)d_in[4];
    const float* Wl1 = (const float*)d_in[5];
    const float* Wr1 = (const float*)d_in[6];
    const float* b1  = (const float*)d_in[7];
    const float* Wl2 = (const float*)d_in[8];
    const float* Wr2 = (const float*)d_in[9];
    const float* b2  = (const float*)d_in[10];
    float* out = (float*)d_out;

    const int* src = ei;
    const int* dst = ei + NE;

    __half *xh, *yh, *zh, *h, *wc;
    int *cnt, *offs, *cursor, *csrc, *bsum;
    cudaGetSymbolAddress((void**)&xh,     g_x);
    cudaGetSymbolAddress((void**)&yh,     g_yh);
    cudaGetSymbolAddress((void**)&zh,     g_zh);
    cudaGetSymbolAddress((void**)&h,      g_h);
    cudaGetSymbolAddress((void**)&wc,     g_wcat);
    cudaGetSymbolAddress((void**)&cnt,    g_cnt);
    cudaGetSymbolAddress((void**)&offs,   g_offs);
    cudaGetSymbolAddress((void**)&cursor, g_cursor);
    cudaGetSymbolAddress((void**)&csrc,   g_csrc);
    cudaGetSymbolAddress((void**)&bsum,   g_bsum);
    __half* wc0 = wc;
    __half* wc1 = wc + 256 * 128;
    __half* wc2 = wc + 2 * 256 * 128;

    const int T = 256;
    dim3 gM(2, NN_PAD / 128);    // N = 256
    dim3 gM1(1, NN_PAD / 128);   // N = 128

    // Fork/join side stream (verified pattern).
    cudaStream_t s2;
    cudaEvent_t evFork, evJoin;
    cudaStreamCreateWithFlags(&s2, cudaStreamNonBlocking);
    cudaEventCreateWithFlags(&evFork, cudaEventDisableTiming);
    cudaEventCreateWithFlags(&evJoin, cudaEventDisableTiming);

    cudaEventRecord(evFork, 0);
    cudaStreamWaitEvent(s2, evFork, 0);

    // ---- main: fp16 prep + layer-0 GEMM (4th kernel launch for ncu) ----
    cvt_x_h<<<(NN_PAD * 16 + T - 1) / T, T>>>((const float4*)x, (uint4*)xh); // 1
    cvt_w_h<<<(2 * 2048 + T - 1) / T, T>>>((const float4*)Wl0,
                                           (const float4*)Wr0,
                                           (uint4*)wc0, 2048);               // 2
    zero_cnt<<<(NN + T - 1) / T, T, 0, s2>>>(cnt);                           // 3 (s2)
    h16gemm_hh<<<gM, T>>>(xh, wc0, yh, zh, 256);                             // 4 <- ncu

    // ---- side stream: CSR build + remaining weight conversions ----
    count_deg<<<(NE + T - 1) / T, T, 0, s2>>>(dst, cnt);
    scan_a<<<NBLK, SCAN_B, 0, s2>>>(cnt, offs, bsum);
    scan_b<<<1, 128, 0, s2>>>(bsum);
    scan_c<<<(NN + T - 1) / T, T, 0, s2>>>(offs, bsum, cursor);
    place_edges<<<(NE + T - 1) / T, T, 0, s2>>>(src, dst, cursor, csrc);
    cvt_w_h<<<(2 * 2048 + T - 1) / T, T, 0, s2>>>((const float4*)Wl1,
                                                  (const float4*)Wr1,
                                                  (uint4*)wc1, 2048);
    cvt_w_h<<<(2 * 1024 + T - 1) / T, T, 0, s2>>>((const float4*)Wl2,
                                                  (const float4*)Wr2,
                                                  (uint4*)wc2, 1024);
    cudaEventRecord(evJoin, s2);
    cudaStreamWaitEvent(0, evJoin, 0);

    // ---- layer 0 combine (writes fp16 h) ----
    agg_combine<16, true><<<(NN_PAD * 16 + T - 1) / T, T>>>(
        (const uint4*)yh, (const uint4*)zh, csrc, offs, b0, (uint4*)h, nullptr);

    // ---- layer 1 ----
    h16gemm_hh<<<gM, T>>>(h, wc1, yh, zh, 256);
    agg_combine<16, true><<<(NN_PAD * 16 + T - 1) / T, T>>>(
        (const uint4*)yh, (const uint4*)zh, csrc, offs, b1, (uint4*)h, nullptr);

    // ---- layer 2 (d_out = 64, no relu, fp32 out) ----
    h16gemm_hh<<<gM1, T>>>(h, wc2, yh, zh, 128);
    agg_combine<8, false><<<(NN * 8 + T - 1) / T, T>>>(
        (const uint4*)yh, (const uint4*)zh, csrc, offs, b2, nullptr, (float4*)out);
}